// round 12
// baseline (speedup 1.0000x reference)
#include <cuda_runtime.h>

// NeuralODE: encoder -> 99 RK4 steps -> decoder at every timestep.
// E=2 elements/thread + MUFU.TANH (R11 = 2338us). THIS REV: wave balance.
// 256 big blocks put 2 blocks on 108 SMs and 1 on 40 (1.16x tail). Same
// 1024 warps as 1024 single-warp blocks spread 7-per-SM nearly uniformly
// (136 SMs x7, 12 x6): critical-SM element count drops 512 -> 448.

#define HID 50
#define LAT 16

typedef unsigned long long u64;

__device__ __forceinline__ u64 pk2(float a, float b) {
    u64 v; asm("mov.b64 %0, {%1,%2};" : "=l"(v) : "f"(a), "f"(b)); return v;
}
__device__ __forceinline__ float2 up2(u64 v) {
    float2 r; asm("mov.b64 {%0,%1}, %2;" : "=f"(r.x), "=f"(r.y) : "l"(v)); return r;
}
__device__ __forceinline__ u64 ffma2(u64 a, u64 b, u64 c) {
    u64 d; asm("fma.rn.f32x2 %0, %1, %2, %3;" : "=l"(d) : "l"(a), "l"(b), "l"(c)); return d;
}
__device__ __forceinline__ u64 fmul2(u64 a, u64 b) {
    u64 d; asm("mul.rn.f32x2 %0, %1, %2;" : "=l"(d) : "l"(a), "l"(b)); return d;
}
__device__ __forceinline__ u64 fadd2(u64 a, u64 b) {
    u64 d; asm("add.rn.f32x2 %0, %1, %2;" : "=l"(d) : "l"(a), "l"(b)); return d;
}

// Hardware tanh (MUFU.TANH): 1 op, ~2^-11 max abs err.
__device__ __forceinline__ float tanh_hw(float x) {
    float r; asm("tanh.approx.f32 %0, %1;" : "=f"(r) : "f"(x)); return r;
}

struct __align__(16) SW {
    float wo1t[HID * LAT];  // wo1t[i*16+k] = Wo1[k][i]
    float wo2 [HID * LAT];  // Wo2[i][j], row-major
    float we2 [HID * LAT];  // We2[i][k], row-major
    float wd1t[HID * LAT];  // wd1t[i*16+k] = Wd1[k][i]
    float bo2[LAT];
    float be2[LAT];
    float bo1[HID];
    float be1[HID];
    float bd1[HID];
    float we1a[HID];        // We1[0][i]
    float we1b[HID];        // We1[1][i]
    float wd2[HID];
    float dt[128];
    float bd2;
};

// dot of 16-dim packed z with a weight row already in registers
__device__ __forceinline__ float rdot(const u64 zp[8], ulonglong2 w0, ulonglong2 w1,
                                      ulonglong2 w2, ulonglong2 w3) {
    u64 a0 = fmul2(zp[0], w0.x);
    u64 a1 = fmul2(zp[1], w0.y);
    a0 = ffma2(zp[2], w1.x, a0);
    a1 = ffma2(zp[3], w1.y, a1);
    a0 = ffma2(zp[4], w2.x, a0);
    a1 = ffma2(zp[5], w2.y, a1);
    a0 = ffma2(zp[6], w3.x, a0);
    a1 = ffma2(zp[7], w3.y, a1);
    float2 p = up2(fadd2(a0, a1));
    return p.x + p.y;
}

// k = tanh(z@Wo1 + bo1) @ Wo2 + bo2  for two elements sharing weight loads
__device__ __forceinline__ void ode_f2(const u64 zA[8], const u64 zB[8],
                                       u64 kA[8], u64 kB[8], const SW& s) {
    const u64* bo2p = (const u64*)s.bo2;
#pragma unroll
    for (int j = 0; j < 8; j++) { kA[j] = bo2p[j]; kB[j] = bo2p[j]; }
#pragma unroll 10
    for (int i = 0; i < HID; i++) {
        const ulonglong2* w = (const ulonglong2*)(s.wo1t + i * LAT);
        ulonglong2 w0 = w[0], w1 = w[1], w2 = w[2], w3 = w[3];
        float b1 = s.bo1[i];
        float hA = tanh_hw(rdot(zA, w0, w1, w2, w3) + b1);
        float hB = tanh_hw(rdot(zB, w0, w1, w2, w3) + b1);
        u64 hA2 = pk2(hA, hA), hB2 = pk2(hB, hB);
        const ulonglong2* v = (const ulonglong2*)(s.wo2 + i * LAT);
#pragma unroll
        for (int j = 0; j < 4; j++) {
            ulonglong2 vv = v[j];
            kA[2 * j]     = ffma2(hA2, vv.x, kA[2 * j]);
            kA[2 * j + 1] = ffma2(hA2, vv.y, kA[2 * j + 1]);
            kB[2 * j]     = ffma2(hB2, vv.x, kB[2 * j]);
            kB[2 * j + 1] = ffma2(hB2, vv.y, kB[2 * j + 1]);
        }
    }
}

// y = relu(z@Wd1 + bd1) @ Wd2 + bd2 for two elements sharing weight loads
__device__ __forceinline__ float2 decode2(const u64 zA[8], const u64 zB[8], const SW& s) {
    float yA = s.bd2, yB = s.bd2;
#pragma unroll 10
    for (int i = 0; i < HID; i++) {
        const ulonglong2* w = (const ulonglong2*)(s.wd1t + i * LAT);
        ulonglong2 w0 = w[0], w1 = w[1], w2 = w[2], w3 = w[3];
        float hA = fmaxf(rdot(zA, w0, w1, w2, w3) + s.bd1[i], 0.0f);
        float hB = fmaxf(rdot(zB, w0, w1, w2, w3) + s.bd1[i], 0.0f);
        float wd = s.wd2[i];
        yA = fmaf(hA, wd, yA);
        yB = fmaf(hB, wd, yB);
    }
    return make_float2(yA, yB);
}

__global__ void __launch_bounds__(32)
node_kernel(const float* __restrict__ x0, const float* __restrict__ t,
            const float* __restrict__ We1, const float* __restrict__ be1,
            const float* __restrict__ We2, const float* __restrict__ be2,
            const float* __restrict__ Wo1, const float* __restrict__ bo1,
            const float* __restrict__ Wo2, const float* __restrict__ bo2,
            const float* __restrict__ Wd1, const float* __restrict__ bd1,
            const float* __restrict__ Wd2, const float* __restrict__ bd2,
            float* __restrict__ out, int Bn, int Tn) {
    __shared__ SW s;
    int tid = threadIdx.x;

    for (int idx = tid; idx < HID * LAT; idx += blockDim.x) {
        int i = idx >> 4, k = idx & 15;
        s.wo1t[idx] = Wo1[k * HID + i];
        s.wd1t[idx] = Wd1[k * HID + i];
        s.wo2[idx]  = Wo2[idx];
        s.we2[idx]  = We2[idx];
    }
    for (int idx = tid; idx < HID; idx += blockDim.x) {
        s.bo1[idx]  = bo1[idx];
        s.be1[idx]  = be1[idx];
        s.bd1[idx]  = bd1[idx];
        s.we1a[idx] = We1[idx];
        s.we1b[idx] = We1[HID + idx];
        s.wd2[idx]  = Wd2[idx];
    }
    for (int idx = tid; idx < LAT; idx += blockDim.x) {
        s.bo2[idx] = bo2[idx];
        s.be2[idx] = be2[idx];
    }
    for (int idx = tid; idx < Tn - 1 && idx < 128; idx += blockDim.x)
        s.dt[idx] = t[idx + 1] - t[idx];
    if (tid == 0) s.bd2 = bd2[0];
    __syncthreads();

    int bA = blockIdx.x * 64 + tid;
    int bB = bA + 32;
    if (bA >= Bn) return;
    bool hasB = (bB < Bn);

    // ---------- Encoder for both elements (shared weight loads) ----------
    float2 xA = ((const float2*)x0)[bA];
    float2 xB = hasB ? ((const float2*)x0)[bB] : make_float2(0.f, 0.f);
    u64 zA[8], zB[8];
    {
        const u64* be2p = (const u64*)s.be2;
#pragma unroll
        for (int j = 0; j < 8; j++) { zA[j] = be2p[j]; zB[j] = be2p[j]; }
#pragma unroll 10
        for (int i = 0; i < HID; i++) {
            float w1a = s.we1a[i], w1b = s.we1b[i], b1 = s.be1[i];
            float hA = fmaxf(fmaf(xA.y, w1b, fmaf(xA.x, w1a, b1)), 0.0f);
            float hB = fmaxf(fmaf(xB.y, w1b, fmaf(xB.x, w1a, b1)), 0.0f);
            u64 hA2 = pk2(hA, hA), hB2 = pk2(hB, hB);
            const ulonglong2* w = (const ulonglong2*)(s.we2 + i * LAT);
#pragma unroll
            for (int j = 0; j < 4; j++) {
                ulonglong2 ww = w[j];
                zA[2 * j]     = ffma2(hA2, ww.x, zA[2 * j]);
                zA[2 * j + 1] = ffma2(hA2, ww.y, zA[2 * j + 1]);
                zB[2 * j]     = ffma2(hB2, ww.x, zB[2 * j]);
                zB[2 * j + 1] = ffma2(hB2, ww.y, zB[2 * j + 1]);
            }
        }
    }

    {
        float2 y = decode2(zA, zB, s);
        out[bA] = y.x;
        if (hasB) out[bB] = y.y;
    }

    // ---------- RK4 time stepping (stages fully unrolled) ----------
    for (int st = 0; st < Tn - 1; ++st) {
        float dt = s.dt[st];
        float h6 = dt * (1.0f / 6.0f);
        float h3 = dt * (1.0f / 3.0f);
        float hf = dt * 0.5f;
        u64 c6 = pk2(h6, h6), c3 = pk2(h3, h3), c2 = pk2(hf, hf), c1 = pk2(dt, dt);

        u64 znA[8], ztA[8], kkA[8];
        u64 znB[8], ztB[8], kkB[8];

        // stage 1
        ode_f2(zA, zB, kkA, kkB, s);
#pragma unroll
        for (int j = 0; j < 8; j++) {
            znA[j] = ffma2(c6, kkA[j], zA[j]);
            ztA[j] = ffma2(c2, kkA[j], zA[j]);
            znB[j] = ffma2(c6, kkB[j], zB[j]);
            ztB[j] = ffma2(c2, kkB[j], zB[j]);
        }
        // stage 2
        ode_f2(ztA, ztB, kkA, kkB, s);
#pragma unroll
        for (int j = 0; j < 8; j++) {
            znA[j] = ffma2(c3, kkA[j], znA[j]);
            ztA[j] = ffma2(c2, kkA[j], zA[j]);
            znB[j] = ffma2(c3, kkB[j], znB[j]);
            ztB[j] = ffma2(c2, kkB[j], zB[j]);
        }
        // stage 3
        ode_f2(ztA, ztB, kkA, kkB, s);
#pragma unroll
        for (int j = 0; j < 8; j++) {
            znA[j] = ffma2(c3, kkA[j], znA[j]);
            ztA[j] = ffma2(c1, kkA[j], zA[j]);
            znB[j] = ffma2(c3, kkB[j], znB[j]);
            ztB[j] = ffma2(c1, kkB[j], zB[j]);
        }
        // stage 4
        ode_f2(ztA, ztB, kkA, kkB, s);
#pragma unroll
        for (int j = 0; j < 8; j++) {
            zA[j] = ffma2(c6, kkA[j], znA[j]);
            zB[j] = ffma2(c6, kkB[j], znB[j]);
        }

        float2 y = decode2(zA, zB, s);
        size_t base = (size_t)(st + 1) * Bn;
        out[base + bA] = y.x;
        if (hasB) out[base + bB] = y.y;
    }
}

extern "C" void kernel_launch(void* const* d_in, const int* in_sizes, int n_in,
                              void* d_out, int out_size) {
    const float* x0  = (const float*)d_in[0];
    const float* t   = (const float*)d_in[1];
    const float* We1 = (const float*)d_in[2];
    const float* be1 = (const float*)d_in[3];
    const float* We2 = (const float*)d_in[4];
    const float* be2 = (const float*)d_in[5];
    const float* Wo1 = (const float*)d_in[6];
    const float* bo1 = (const float*)d_in[7];
    const float* Wo2 = (const float*)d_in[8];
    const float* bo2 = (const float*)d_in[9];
    const float* Wd1 = (const float*)d_in[10];
    const float* bd1 = (const float*)d_in[11];
    const float* Wd2 = (const float*)d_in[12];
    const float* bd2 = (const float*)d_in[13];

    int Bn = in_sizes[0] / 2;   // x0 is (B, 2)
    int Tn = in_sizes[1];       // t is (T,)

    int threads = 32;                // 1 warp per block -> even 7/SM spread
    int blocks = (Bn + 63) / 64;     // 2 elements per thread, 64 per block
    node_kernel<<<blocks, threads>>>(x0, t, We1, be1, We2, be2, Wo1, bo1,
                                     Wo2, bo2, Wd1, bd1, Wd2, bd2,
                                     (float*)d_out, Bn, Tn);
}

// round 13
// speedup vs baseline: 1.0162x; 1.0162x over previous
#include <cuda_runtime.h>

// NeuralODE: encoder -> 99 RK4 steps -> decoder at every timestep.
// E=2 elements/thread + MUFU.TANH (R11 = 2338us). THIS REV: attack latency
// exposure. Grid caps warps at 1024 (6.9/SM) so registers are free until
// ~250: __launch_bounds__(128,1) unlocks the full file, and ode_f2/decode2
// are explicitly software-pipelined (row i+1's weights prefetched before
// row i's tanh; wo2 row loaded before the tanh it consumes).

#define HID 50
#define LAT 16

typedef unsigned long long u64;

__device__ __forceinline__ u64 pk2(float a, float b) {
    u64 v; asm("mov.b64 %0, {%1,%2};" : "=l"(v) : "f"(a), "f"(b)); return v;
}
__device__ __forceinline__ float2 up2(u64 v) {
    float2 r; asm("mov.b64 {%0,%1}, %2;" : "=f"(r.x), "=f"(r.y) : "l"(v)); return r;
}
__device__ __forceinline__ u64 ffma2(u64 a, u64 b, u64 c) {
    u64 d; asm("fma.rn.f32x2 %0, %1, %2, %3;" : "=l"(d) : "l"(a), "l"(b), "l"(c)); return d;
}
__device__ __forceinline__ u64 fmul2(u64 a, u64 b) {
    u64 d; asm("mul.rn.f32x2 %0, %1, %2;" : "=l"(d) : "l"(a), "l"(b)); return d;
}
__device__ __forceinline__ u64 fadd2(u64 a, u64 b) {
    u64 d; asm("add.rn.f32x2 %0, %1, %2;" : "=l"(d) : "l"(a), "l"(b)); return d;
}

// Hardware tanh (MUFU.TANH): 1 op, ~2^-11 max abs err.
__device__ __forceinline__ float tanh_hw(float x) {
    float r; asm("tanh.approx.f32 %0, %1;" : "=f"(r) : "f"(x)); return r;
}

struct __align__(16) SW {
    float wo1t[HID * LAT];  // wo1t[i*16+k] = Wo1[k][i]
    float wo2 [HID * LAT];  // Wo2[i][j], row-major
    float we2 [HID * LAT];  // We2[i][k], row-major
    float wd1t[HID * LAT];  // wd1t[i*16+k] = Wd1[k][i]
    float bo2[LAT];
    float be2[LAT];
    float bo1[HID];
    float be1[HID];
    float bd1[HID];
    float we1a[HID];        // We1[0][i]
    float we1b[HID];        // We1[1][i]
    float wd2[HID];
    float dt[128];
    float bd2;
};

// dot of 16-dim packed z with a weight row already in registers
__device__ __forceinline__ float rdot(const u64 zp[8], ulonglong2 w0, ulonglong2 w1,
                                      ulonglong2 w2, ulonglong2 w3) {
    u64 a0 = fmul2(zp[0], w0.x);
    u64 a1 = fmul2(zp[1], w0.y);
    a0 = ffma2(zp[2], w1.x, a0);
    a1 = ffma2(zp[3], w1.y, a1);
    a0 = ffma2(zp[4], w2.x, a0);
    a1 = ffma2(zp[5], w2.y, a1);
    a0 = ffma2(zp[6], w3.x, a0);
    a1 = ffma2(zp[7], w3.y, a1);
    float2 p = up2(fadd2(a0, a1));
    return p.x + p.y;
}

// k = tanh(z@Wo1 + bo1) @ Wo2 + bo2  for two elements sharing weight loads.
// Software-pipelined: row i+1's wo1t prefetched before row i's tanh;
// wo2 row loaded before the tanh it consumes.
__device__ __forceinline__ void ode_f2(const u64 zA[8], const u64 zB[8],
                                       u64 kA[8], u64 kB[8], const SW& s) {
    const u64* bo2p = (const u64*)s.bo2;
#pragma unroll
    for (int j = 0; j < 8; j++) { kA[j] = bo2p[j]; kB[j] = bo2p[j]; }

    const ulonglong2* w = (const ulonglong2*)s.wo1t;
    ulonglong2 p0 = w[0], p1 = w[1], p2 = w[2], p3 = w[3];
#pragma unroll 10
    for (int i = 0; i < HID; i++) {
        ulonglong2 w0 = p0, w1 = p1, w2 = p2, w3 = p3;
        // prefetch next row (wraps to row 0 on last iter; harmless)
        const ulonglong2* wn = (const ulonglong2*)(s.wo1t + ((i + 1) % HID) * LAT);
        p0 = wn[0]; p1 = wn[1]; p2 = wn[2]; p3 = wn[3];
        // load wo2 row BEFORE tanh (independent of the dot)
        const ulonglong2* v = (const ulonglong2*)(s.wo2 + i * LAT);
        ulonglong2 v0 = v[0], v1 = v[1], v2 = v[2], v3 = v[3];

        float b1 = s.bo1[i];
        float hA = tanh_hw(rdot(zA, w0, w1, w2, w3) + b1);
        float hB = tanh_hw(rdot(zB, w0, w1, w2, w3) + b1);
        u64 hA2 = pk2(hA, hA), hB2 = pk2(hB, hB);

        kA[0] = ffma2(hA2, v0.x, kA[0]);
        kA[1] = ffma2(hA2, v0.y, kA[1]);
        kA[2] = ffma2(hA2, v1.x, kA[2]);
        kA[3] = ffma2(hA2, v1.y, kA[3]);
        kA[4] = ffma2(hA2, v2.x, kA[4]);
        kA[5] = ffma2(hA2, v2.y, kA[5]);
        kA[6] = ffma2(hA2, v3.x, kA[6]);
        kA[7] = ffma2(hA2, v3.y, kA[7]);
        kB[0] = ffma2(hB2, v0.x, kB[0]);
        kB[1] = ffma2(hB2, v0.y, kB[1]);
        kB[2] = ffma2(hB2, v1.x, kB[2]);
        kB[3] = ffma2(hB2, v1.y, kB[3]);
        kB[4] = ffma2(hB2, v2.x, kB[4]);
        kB[5] = ffma2(hB2, v2.y, kB[5]);
        kB[6] = ffma2(hB2, v3.x, kB[6]);
        kB[7] = ffma2(hB2, v3.y, kB[7]);
    }
}

// y = relu(z@Wd1 + bd1) @ Wd2 + bd2, software-pipelined like ode_f2.
__device__ __forceinline__ float2 decode2(const u64 zA[8], const u64 zB[8], const SW& s) {
    float yA = s.bd2, yB = s.bd2;
    const ulonglong2* w = (const ulonglong2*)s.wd1t;
    ulonglong2 p0 = w[0], p1 = w[1], p2 = w[2], p3 = w[3];
#pragma unroll 10
    for (int i = 0; i < HID; i++) {
        ulonglong2 w0 = p0, w1 = p1, w2 = p2, w3 = p3;
        const ulonglong2* wn = (const ulonglong2*)(s.wd1t + ((i + 1) % HID) * LAT);
        p0 = wn[0]; p1 = wn[1]; p2 = wn[2]; p3 = wn[3];
        float hA = fmaxf(rdot(zA, w0, w1, w2, w3) + s.bd1[i], 0.0f);
        float hB = fmaxf(rdot(zB, w0, w1, w2, w3) + s.bd1[i], 0.0f);
        float wd = s.wd2[i];
        yA = fmaf(hA, wd, yA);
        yB = fmaf(hB, wd, yB);
    }
    return make_float2(yA, yB);
}

__global__ void __launch_bounds__(128, 1)
node_kernel(const float* __restrict__ x0, const float* __restrict__ t,
            const float* __restrict__ We1, const float* __restrict__ be1,
            const float* __restrict__ We2, const float* __restrict__ be2,
            const float* __restrict__ Wo1, const float* __restrict__ bo1,
            const float* __restrict__ Wo2, const float* __restrict__ bo2,
            const float* __restrict__ Wd1, const float* __restrict__ bd1,
            const float* __restrict__ Wd2, const float* __restrict__ bd2,
            float* __restrict__ out, int Bn, int Tn) {
    __shared__ SW s;
    int tid = threadIdx.x;

    for (int idx = tid; idx < HID * LAT; idx += blockDim.x) {
        int i = idx >> 4, k = idx & 15;
        s.wo1t[idx] = Wo1[k * HID + i];
        s.wd1t[idx] = Wd1[k * HID + i];
        s.wo2[idx]  = Wo2[idx];
        s.we2[idx]  = We2[idx];
    }
    for (int idx = tid; idx < HID; idx += blockDim.x) {
        s.bo1[idx]  = bo1[idx];
        s.be1[idx]  = be1[idx];
        s.bd1[idx]  = bd1[idx];
        s.we1a[idx] = We1[idx];
        s.we1b[idx] = We1[HID + idx];
        s.wd2[idx]  = Wd2[idx];
    }
    for (int idx = tid; idx < LAT; idx += blockDim.x) {
        s.bo2[idx] = bo2[idx];
        s.be2[idx] = be2[idx];
    }
    for (int idx = tid; idx < Tn - 1 && idx < 128; idx += blockDim.x)
        s.dt[idx] = t[idx + 1] - t[idx];
    if (tid == 0) s.bd2 = bd2[0];
    __syncthreads();

    int bA = blockIdx.x * 256 + tid;
    int bB = bA + 128;
    if (bA >= Bn) return;
    bool hasB = (bB < Bn);

    // ---------- Encoder for both elements (shared weight loads) ----------
    float2 xA = ((const float2*)x0)[bA];
    float2 xB = hasB ? ((const float2*)x0)[bB] : make_float2(0.f, 0.f);
    u64 zA[8], zB[8];
    {
        const u64* be2p = (const u64*)s.be2;
#pragma unroll
        for (int j = 0; j < 8; j++) { zA[j] = be2p[j]; zB[j] = be2p[j]; }
#pragma unroll 10
        for (int i = 0; i < HID; i++) {
            float w1a = s.we1a[i], w1b = s.we1b[i], b1 = s.be1[i];
            float hA = fmaxf(fmaf(xA.y, w1b, fmaf(xA.x, w1a, b1)), 0.0f);
            float hB = fmaxf(fmaf(xB.y, w1b, fmaf(xB.x, w1a, b1)), 0.0f);
            u64 hA2 = pk2(hA, hA), hB2 = pk2(hB, hB);
            const ulonglong2* w = (const ulonglong2*)(s.we2 + i * LAT);
#pragma unroll
            for (int j = 0; j < 4; j++) {
                ulonglong2 ww = w[j];
                zA[2 * j]     = ffma2(hA2, ww.x, zA[2 * j]);
                zA[2 * j + 1] = ffma2(hA2, ww.y, zA[2 * j + 1]);
                zB[2 * j]     = ffma2(hB2, ww.x, zB[2 * j]);
                zB[2 * j + 1] = ffma2(hB2, ww.y, zB[2 * j + 1]);
            }
        }
    }

    {
        float2 y = decode2(zA, zB, s);
        out[bA] = y.x;
        if (hasB) out[bB] = y.y;
    }

    // ---------- RK4 time stepping (stages fully unrolled) ----------
    for (int st = 0; st < Tn - 1; ++st) {
        float dt = s.dt[st];
        float h6 = dt * (1.0f / 6.0f);
        float h3 = dt * (1.0f / 3.0f);
        float hf = dt * 0.5f;
        u64 c6 = pk2(h6, h6), c3 = pk2(h3, h3), c2 = pk2(hf, hf), c1 = pk2(dt, dt);

        u64 znA[8], ztA[8], kkA[8];
        u64 znB[8], ztB[8], kkB[8];

        // stage 1
        ode_f2(zA, zB, kkA, kkB, s);
#pragma unroll
        for (int j = 0; j < 8; j++) {
            znA[j] = ffma2(c6, kkA[j], zA[j]);
            ztA[j] = ffma2(c2, kkA[j], zA[j]);
            znB[j] = ffma2(c6, kkB[j], zB[j]);
            ztB[j] = ffma2(c2, kkB[j], zB[j]);
        }
        // stage 2
        ode_f2(ztA, ztB, kkA, kkB, s);
#pragma unroll
        for (int j = 0; j < 8; j++) {
            znA[j] = ffma2(c3, kkA[j], znA[j]);
            ztA[j] = ffma2(c2, kkA[j], zA[j]);
            znB[j] = ffma2(c3, kkB[j], znB[j]);
            ztB[j] = ffma2(c2, kkB[j], zB[j]);
        }
        // stage 3
        ode_f2(ztA, ztB, kkA, kkB, s);
#pragma unroll
        for (int j = 0; j < 8; j++) {
            znA[j] = ffma2(c3, kkA[j], znA[j]);
            ztA[j] = ffma2(c1, kkA[j], zA[j]);
            znB[j] = ffma2(c3, kkB[j], znB[j]);
            ztB[j] = ffma2(c1, kkB[j], zB[j]);
        }
        // stage 4
        ode_f2(ztA, ztB, kkA, kkB, s);
#pragma unroll
        for (int j = 0; j < 8; j++) {
            zA[j] = ffma2(c6, kkA[j], znA[j]);
            zB[j] = ffma2(c6, kkB[j], znB[j]);
        }

        float2 y = decode2(zA, zB, s);
        size_t base = (size_t)(st + 1) * Bn;
        out[base + bA] = y.x;
        if (hasB) out[base + bB] = y.y;
    }
}

extern "C" void kernel_launch(void* const* d_in, const int* in_sizes, int n_in,
                              void* d_out, int out_size) {
    const float* x0  = (const float*)d_in[0];
    const float* t   = (const float*)d_in[1];
    const float* We1 = (const float*)d_in[2];
    const float* be1 = (const float*)d_in[3];
    const float* We2 = (const float*)d_in[4];
    const float* be2 = (const float*)d_in[5];
    const float* Wo1 = (const float*)d_in[6];
    const float* bo1 = (const float*)d_in[7];
    const float* Wo2 = (const float*)d_in[8];
    const float* bo2 = (const float*)d_in[9];
    const float* Wd1 = (const float*)d_in[10];
    const float* bd1 = (const float*)d_in[11];
    const float* Wd2 = (const float*)d_in[12];
    const float* bd2 = (const float*)d_in[13];

    int Bn = in_sizes[0] / 2;   // x0 is (B, 2)
    int Tn = in_sizes[1];       // t is (T,)

    int threads = 128;
    int blocks = (Bn + 255) / 256;   // 2 elements per thread
    node_kernel<<<blocks, threads>>>(x0, t, We1, be1, We2, be2, Wo1, bo1,
                                     Wo2, bo2, Wd1, bd1, Wd2, bd2,
                                     (float*)d_out, Bn, Tn);
}